// round 5
// baseline (speedup 1.0000x reference)
#include <cuda_runtime.h>
#include <math.h>

#define N_ROWS   16384
#define ACTIONS  64
#define EMB      32
#define DELTA    16
#define EPSF     1e-5f
#define NB1      128
#define ROWS_PER_B1 (N_ROWS / NB1)   // 128

// Scratch (no allocation allowed in kernel_launch): partial sums + BN params.
__device__ float g_psum[NB1][ACTIONS];
__device__ float g_psq [NB1][ACTIONS];
__device__ float g_scale[ACTIONS];
__device__ float g_shift[ACTIONS];

// ---------------------------------------------------------------------------
// Kernel 1: per-block partial sum / sumsq per action column.
// float4 loads, explicit 8-deep load batch so ptxas keeps MLP=8.
// Thread layout: c4 = tid & 15 (float4 column group), r = tid >> 4 (row 0..15).
// Block covers 128 rows; thread reads rows r, r+16, ..., r+112 (8 x LDG.128).
// Deterministic: fixed-order reductions, no atomics.
// ---------------------------------------------------------------------------
__global__ __launch_bounds__(256) void bn_partial(const float* __restrict__ x)
{
    const int tid = threadIdx.x;
    const int c4  = tid & 15;
    const int r   = tid >> 4;
    const int b   = blockIdx.x;

    const float4* px = reinterpret_cast<const float4*>(x)
                     + (size_t)(b * ROWS_PER_B1 + r) * (ACTIONS / 4) + c4;

    float4 v[8];
#pragma unroll
    for (int k = 0; k < 8; k++)
        v[k] = __ldg(px + (size_t)k * 16 * (ACTIONS / 4));   // +16 rows each

    float4 s = {0.f, 0.f, 0.f, 0.f};
    float4 q = {0.f, 0.f, 0.f, 0.f};
#pragma unroll
    for (int k = 0; k < 8; k++) {
        s.x += v[k].x; q.x += v[k].x * v[k].x;
        s.y += v[k].y; q.y += v[k].y * v[k].y;
        s.z += v[k].z; q.z += v[k].z * v[k].z;
        s.w += v[k].w; q.w += v[k].w * v[k].w;
    }

    __shared__ float4 ss[16][16];
    __shared__ float4 sq[16][16];
    ss[r][c4] = s;
    sq[r][c4] = q;
    __syncthreads();

    if (tid < ACTIONS) {
        const int c = tid;
        const int cc = c >> 2, ce = c & 3;
        float ts = 0.f, tq = 0.f;
#pragma unroll
        for (int r2 = 0; r2 < 16; r2++) {
            ts += reinterpret_cast<const float*>(&ss[r2][cc])[ce];
            tq += reinterpret_cast<const float*>(&sq[r2][cc])[ce];
        }
        g_psum[b][c] = ts;
        g_psq [b][c] = tq;
    }
}

// ---------------------------------------------------------------------------
// Kernel 2: finalize BN stats -> per-column scale/shift.
// 256 threads: 4 reducers per column (32 partials each), fixed-order combine.
// ---------------------------------------------------------------------------
__global__ __launch_bounds__(256) void bn_finalize(const float* __restrict__ wgt,
                                                   const float* __restrict__ bias)
{
    const int tid = threadIdx.x;
    const int c   = tid & 63;
    const int j   = tid >> 6;   // 0..3

    float s = 0.f, q = 0.f;
#pragma unroll 8
    for (int k = 0; k < NB1 / 4; k++) {
        s += g_psum[j * (NB1 / 4) + k][c];
        q += g_psq [j * (NB1 / 4) + k][c];
    }

    __shared__ float ss[4][ACTIONS];
    __shared__ float sq[4][ACTIONS];
    ss[j][c] = s;
    sq[j][c] = q;
    __syncthreads();

    if (tid < ACTIONS) {
        float ts = ((ss[0][c] + ss[1][c]) + ss[2][c]) + ss[3][c];
        float tq = ((sq[0][c] + sq[1][c]) + sq[2][c]) + sq[3][c];
        const float inv_n = 1.0f / (float)N_ROWS;
        float mean = ts * inv_n;
        float var  = fmaf(-mean, mean, tq * inv_n);   // E[x^2] - mean^2
        float sc   = wgt[c] * rsqrtf(var + EPSF);
        g_scale[c] = sc;
        g_shift[c] = fmaf(-mean, sc, bias[c]);
    }
}

// ---------------------------------------------------------------------------
// Kernel 3: main spline-embedding pass.
//  - warp = 4 (row, action) pairs; 8 lanes per pair (one float4 of EMB=32).
//  - tanh/index computed ONCE per pair (lanes 0..3), broadcast via shfl
//    (was 8x redundant -> 8.4M tanh; now 1.05M).
//  - blockIdx.y = action => per-block table slice = 33 rows * 128B = 4.2 KB,
//    L1-resident gathers; each LDG.128 touches 4 lines/warp.
//  - xh = xl + 1 always, so bh row = bl row + 64; wl = 1 - wh exactly.
//  - __stcs streaming stores keep the 134 MB write stream out of L2.
// ---------------------------------------------------------------------------
__global__ __launch_bounds__(256) void spline_main(const float* __restrict__ x,
                                                   const float* __restrict__ emb,
                                                   float* __restrict__ out)
{
    const int tid   = threadIdx.x;
    const int lane  = tid & 31;
    const int wid   = tid >> 5;           // warp 0..7
    const int lane8 = lane & 7;           // float4 group within EMB
    const int g     = lane >> 3;          // pair within warp (0..3)
    const int a     = blockIdx.y;
    const int row_base = blockIdx.x * 32 + wid * 4;

    // Compute phase: lanes 0..3 each handle one pair.
    float wh_v = 0.f;
    int   li_v = 0;
    if (lane < 4) {
        const float sc = g_scale[a];
        const float sh = g_shift[a];
        const float xv = __ldg(x + (size_t)(row_base + lane) * ACTIONS + a);
        float t = tanhf(fmaf(xv, sc, sh));
        t = fminf(fmaxf(t, -1.0f + 1e-5f), 1.0f - 1e-5f);
        const float f   = t * (float)DELTA;     // exact (power-of-2 scale)
        const float xlf = floorf(f);
        wh_v = f - xlf;                          // = DELTA*(t - xl), exact
        li_v = (((int)xlf) + DELTA) * ACTIONS + a;
    }
    const float wh = __shfl_sync(0xffffffffu, wh_v, g);
    const int   li = __shfl_sync(0xffffffffu, li_v, g);
    const float wl = 1.0f - wh;                  // = DELTA*(xh - t)

    const float4* bl4 = reinterpret_cast<const float4*>(emb)
                      + (size_t)li * (EMB / 4) + lane8;
    const float4 bl = __ldg(bl4);
    const float4 bh = __ldg(bl4 + (size_t)ACTIONS * (EMB / 4)); // row + 64

    float4 h;
    h.x = bh.x * wh + bl.x * wl;
    h.y = bh.y * wh + bl.y * wl;
    h.z = bh.z * wh + bl.z * wl;
    h.w = bh.w * wh + bl.w * wl;

    float4* o4 = reinterpret_cast<float4*>(out)
               + (size_t)((row_base + g) * ACTIONS + a) * (EMB / 4) + lane8;
    __stcs(o4, h);
}

// ---------------------------------------------------------------------------
// Launch: x, bn_weight, bn_bias, emb_table  ->  out [n, ACTIONS, EMB] fp32
// ---------------------------------------------------------------------------
extern "C" void kernel_launch(void* const* d_in, const int* in_sizes, int n_in,
                              void* d_out, int out_size)
{
    const float* x    = (const float*)d_in[0];
    const float* wgt  = (const float*)d_in[1];
    const float* bias = (const float*)d_in[2];
    const float* emb  = (const float*)d_in[3];
    float* out        = (float*)d_out;

    bn_partial<<<NB1, 256>>>(x);
    bn_finalize<<<1, 256>>>(wgt, bias);

    dim3 grid(N_ROWS / 32, ACTIONS);
    spline_main<<<grid, 256>>>(x, emb, out);
}